// round 1
// baseline (speedup 1.0000x reference)
#include <cuda_runtime.h>
#include <math.h>

#define TT 2048
#define DD 2048
#define HH 16
#define DHD 128
#define FFD 8192

// ---------------- scratch (device globals: no allocation allowed) ----------
__device__ float g_xn [TT * DD];
__device__ float g_q  [TT * DD];
__device__ float g_k  [TT * DD];
__device__ float g_v  [TT * DD];
__device__ float g_ctx[TT * DD];
__device__ float g_ffh[TT * FFD];

// ---------------- LayerNorm ------------------------------------------------
__global__ void layernorm_kernel(const float* __restrict__ x,
                                 const float* __restrict__ scale,
                                 const float* __restrict__ offset,
                                 float* __restrict__ xn) {
    int row = blockIdx.x;
    int tid = threadIdx.x;
    const float* xr = x + (size_t)row * DD;
    float vals[8];
    float s = 0.f;
#pragma unroll
    for (int i = 0; i < 8; i++) { vals[i] = xr[tid + i * 256]; s += vals[i]; }
    __shared__ float red[256];
    red[tid] = s; __syncthreads();
#pragma unroll
    for (int off = 128; off > 0; off >>= 1) {
        if (tid < off) red[tid] += red[tid + off];
        __syncthreads();
    }
    float mean = red[0] * (1.0f / DD);
    __syncthreads();
    float vs = 0.f;
#pragma unroll
    for (int i = 0; i < 8; i++) { float d = vals[i] - mean; vs += d * d; }
    red[tid] = vs; __syncthreads();
#pragma unroll
    for (int off = 128; off > 0; off >>= 1) {
        if (tid < off) red[tid] += red[tid + off];
        __syncthreads();
    }
    float var = red[0] * (1.0f / DD);
    float inv = rsqrtf(var + 1e-5f);
    float* xo = xn + (size_t)row * DD;
#pragma unroll
    for (int i = 0; i < 8; i++) {
        int c = tid + i * 256;
        xo[c] = scale[c] * inv * (vals[i] - mean) + offset[c];
    }
}

// ---------------- RoPE (GPT-J rotate-every-two, first 64 dims) -------------
__global__ void rope_kernel(float* __restrict__ q, float* __restrict__ k) {
    int idx = blockIdx.x * blockDim.x + threadIdx.x;   // T*H*32 threads
    int j = idx & 31;
    int h = (idx >> 5) & 15;
    int t = idx >> 9;
    float inv = (float)pow(10000.0, -(double)(2 * j) / 64.0);
    float ang = (float)t * inv;                        // fp32 product, like ref
    float c = cosf(ang), s = sinf(ang);
    int base = t * DD + h * DHD + 2 * j;
    float qe = q[base], qo = q[base + 1];
    q[base]     = qe * c - qo * s;
    q[base + 1] = qo * c + qe * s;
    float ke = k[base], ko = k[base + 1];
    k[base]     = ke * c - ko * s;
    k[base + 1] = ko * c + ke * s;
}

// ---------------- GELU (tanh approx, jax.nn.gelu default) ------------------
__device__ __forceinline__ float gelu_tanh(float v) {
    float u = 0.7978845608028654f * (v + 0.044715f * v * v * v);
    return 0.5f * v * (1.0f + tanhf(u));
}

// ---------------- SGEMM 128x128x8, 8x8/thread, 256 threads -----------------
// mode 0: C = A*B
// mode 1: C = gelu(A*B + bias)
// mode 2: C = A*B + res
// mode 3: C = C + A*B + bias
__global__ void sgemm_kernel(const float* __restrict__ A,
                             const float* __restrict__ B,
                             float* __restrict__ C,
                             int M, int N, int K,
                             const float* __restrict__ bias,
                             const float* __restrict__ res,
                             int mode) {
    __shared__ float As[8][128];
    __shared__ float Bs[8][128];

    int m0 = blockIdx.y * 128;
    int n0 = blockIdx.x * 128;
    int tid = threadIdx.x;
    int ty = tid >> 4, tx = tid & 15;

    int a_row = tid >> 1;            // 0..127
    int a_col = (tid & 1) << 2;      // 0 or 4
    int b_row = tid >> 5;            // 0..7
    int b_col = (tid & 31) << 2;     // 0..124

    const float* Aptr = A + (size_t)(m0 + a_row) * K + a_col;
    const float* Bptr = B + (size_t)b_row * N + n0 + b_col;

    float acc[8][8];
#pragma unroll
    for (int i = 0; i < 8; i++)
#pragma unroll
        for (int j = 0; j < 8; j++) acc[i][j] = 0.f;

    for (int k0 = 0; k0 < K; k0 += 8) {
        float4 av = *(const float4*)(Aptr + k0);
        As[a_col + 0][a_row] = av.x;
        As[a_col + 1][a_row] = av.y;
        As[a_col + 2][a_row] = av.z;
        As[a_col + 3][a_row] = av.w;
        *(float4*)&Bs[b_row][b_col] = *(const float4*)(Bptr + (size_t)k0 * N);
        __syncthreads();
#pragma unroll
        for (int kk = 0; kk < 8; kk++) {
            float ra[8], rb[8];
            *(float4*)&ra[0] = *(float4*)&As[kk][ty * 8];
            *(float4*)&ra[4] = *(float4*)&As[kk][ty * 8 + 4];
            *(float4*)&rb[0] = *(float4*)&Bs[kk][tx * 8];
            *(float4*)&rb[4] = *(float4*)&Bs[kk][tx * 8 + 4];
#pragma unroll
            for (int i = 0; i < 8; i++)
#pragma unroll
                for (int j = 0; j < 8; j++)
                    acc[i][j] += ra[i] * rb[j];
        }
        __syncthreads();
    }

#pragma unroll
    for (int i = 0; i < 8; i++) {
        int r = m0 + ty * 8 + i;
        float* crow = C + (size_t)r * N + n0 + tx * 8;
        if (mode == 0) {
#pragma unroll
            for (int j = 0; j < 8; j++) crow[j] = acc[i][j];
        } else if (mode == 1) {
#pragma unroll
            for (int j = 0; j < 8; j++) {
                float v = acc[i][j] + bias[n0 + tx * 8 + j];
                crow[j] = gelu_tanh(v);
            }
        } else if (mode == 2) {
            const float* rrow = res + (size_t)r * N + n0 + tx * 8;
#pragma unroll
            for (int j = 0; j < 8; j++) crow[j] = acc[i][j] + rrow[j];
        } else {
#pragma unroll
            for (int j = 0; j < 8; j++)
                crow[j] = crow[j] + acc[i][j] + bias[n0 + tx * 8 + j];
        }
    }
}

// ---------------- Flash attention (causal, fp32, 64x64 tiles) --------------
#define KP 129
#define SP 65
#define ATTN_SMEM ((64 * 128 + 64 * 128 + 64 * KP + 64 * SP) * 4)

__global__ void attn_kernel(const float* __restrict__ q,
                            const float* __restrict__ k,
                            const float* __restrict__ v,
                            float* __restrict__ ctx) {
    extern __shared__ float sm[];
    float* Qs = sm;                 // 64 x 128
    float* Vs = Qs + 64 * 128;      // 64 x 128
    float* Ks = Vs + 64 * 128;      // 64 x KP (padded, scalar access)
    float* Ss = Ks + 64 * KP;       // 64 x SP

    int qt = blockIdx.x, h = blockIdx.y;
    int tid = threadIdx.x;
    int q0 = qt * 64;

    for (int i = tid; i < 64 * 32; i += 256) {
        int r = i >> 5, c4 = (i & 31) << 2;
        *(float4*)&Qs[r * 128 + c4] =
            *(const float4*)&q[(size_t)(q0 + r) * DD + h * DHD + c4];
    }

    const int orow = tid >> 2;          // 0..63
    const int oc0  = (tid & 3) << 5;    // 0,32,64,96
    const int sr   = (tid >> 4) << 2;   // 0..60
    const int sc   = (tid & 15) << 2;   // 0..60
    const int pc0  = (tid & 3) << 4;    // softmax col chunk

    float O[32];
#pragma unroll
    for (int i = 0; i < 32; i++) O[i] = 0.f;
    float m_prev = -1e30f, l = 0.f;
    const float sm_scale = 0.08838834764831845f;  // 1/sqrt(128)

    for (int kt = 0; kt <= qt; kt++) {
        __syncthreads();
        for (int i = tid; i < 64 * 32; i += 256) {
            int r = i >> 5, c4 = (i & 31) << 2;
            size_t g = (size_t)(kt * 64 + r) * DD + h * DHD + c4;
            float4 kv = *(const float4*)&k[g];
            Ks[r * KP + c4 + 0] = kv.x;
            Ks[r * KP + c4 + 1] = kv.y;
            Ks[r * KP + c4 + 2] = kv.z;
            Ks[r * KP + c4 + 3] = kv.w;
            *(float4*)&Vs[r * 128 + c4] = *(const float4*)&v[g];
        }
        __syncthreads();

        // S = Q K^T  (each thread 4x4)
        float acc[4][4];
#pragma unroll
        for (int i = 0; i < 4; i++)
#pragma unroll
            for (int j = 0; j < 4; j++) acc[i][j] = 0.f;
        for (int c = 0; c < 128; c++) {
            float qa[4], kb[4];
#pragma unroll
            for (int i = 0; i < 4; i++) qa[i] = Qs[(sr + i) * 128 + c];
#pragma unroll
            for (int j = 0; j < 4; j++) kb[j] = Ks[(sc + j) * KP + c];
#pragma unroll
            for (int i = 0; i < 4; i++)
#pragma unroll
                for (int j = 0; j < 4; j++) acc[i][j] += qa[i] * kb[j];
        }
        bool diag = (kt == qt);
#pragma unroll
        for (int i = 0; i < 4; i++)
#pragma unroll
            for (int j = 0; j < 4; j++) {
                float sv = acc[i][j] * sm_scale;
                if (diag && (kt * 64 + sc + j > q0 + sr + i)) sv = -1e9f;
                Ss[(sr + i) * SP + sc + j] = sv;
            }
        __syncthreads();

        // online softmax: row = orow, 4 threads per row
        float mloc = -1e30f;
#pragma unroll
        for (int c = 0; c < 16; c++)
            mloc = fmaxf(mloc, Ss[orow * SP + pc0 + c]);
        mloc = fmaxf(mloc, __shfl_xor_sync(0xffffffffu, mloc, 1));
        mloc = fmaxf(mloc, __shfl_xor_sync(0xffffffffu, mloc, 2));
        float m_new = fmaxf(m_prev, mloc);
        float corr = __expf(m_prev - m_new);
        float psum = 0.f;
#pragma unroll
        for (int c = 0; c < 16; c++) {
            float p = __expf(Ss[orow * SP + pc0 + c] - m_new);
            Ss[orow * SP + pc0 + c] = p;
            psum += p;
        }
        psum += __shfl_xor_sync(0xffffffffu, psum, 1);
        psum += __shfl_xor_sync(0xffffffffu, psum, 2);
        l = l * corr + psum;
        m_prev = m_new;
#pragma unroll
        for (int i = 0; i < 32; i++) O[i] *= corr;
        __syncthreads();

        // O += P * V  (thread owns row=orow, 32 contiguous output dims)
#pragma unroll 4
        for (int j = 0; j < 64; j++) {
            float p = Ss[orow * SP + j];
            const float4* vv = (const float4*)&Vs[j * 128 + oc0];
#pragma unroll
            for (int cc = 0; cc < 8; cc++) {
                float4 v4 = vv[cc];
                O[cc * 4 + 0] += p * v4.x;
                O[cc * 4 + 1] += p * v4.y;
                O[cc * 4 + 2] += p * v4.z;
                O[cc * 4 + 3] += p * v4.w;
            }
        }
    }

    float invl = 1.0f / l;
#pragma unroll
    for (int i = 0; i < 32; i++) O[i] *= invl;
    float* dst = &ctx[(size_t)(q0 + orow) * DD + h * DHD + oc0];
#pragma unroll
    for (int cc = 0; cc < 8; cc++)
        *(float4*)&dst[cc * 4] = *(float4*)&O[cc * 4];
}

// ---------------- launch ----------------------------------------------------
extern "C" void kernel_launch(void* const* d_in, const int* in_sizes, int n_in,
                              void* d_out, int out_size) {
    const float* x      = (const float*)d_in[0];
    // d_in[1] attn_bias: constant shift pre-softmax -> no effect, skipped
    const float* scale  = (const float*)d_in[2];
    const float* offset = (const float*)d_in[3];
    const float* wq     = (const float*)d_in[4];
    const float* wk     = (const float*)d_in[5];
    const float* wv     = (const float*)d_in[6];
    const float* wo     = (const float*)d_in[7];
    const float* w1     = (const float*)d_in[8];
    const float* b1     = (const float*)d_in[9];
    const float* w2     = (const float*)d_in[10];
    const float* b2     = (const float*)d_in[11];
    float* out = (float*)d_out;

    float *xn, *q, *k, *v, *ctx, *ffh;
    cudaGetSymbolAddress((void**)&xn,  g_xn);
    cudaGetSymbolAddress((void**)&q,   g_q);
    cudaGetSymbolAddress((void**)&k,   g_k);
    cudaGetSymbolAddress((void**)&v,   g_v);
    cudaGetSymbolAddress((void**)&ctx, g_ctx);
    cudaGetSymbolAddress((void**)&ffh, g_ffh);

    cudaFuncSetAttribute(attn_kernel,
                         cudaFuncAttributeMaxDynamicSharedMemorySize, ATTN_SMEM);

    layernorm_kernel<<<TT, 256>>>(x, scale, offset, xn);

    dim3 gD(DD / 128, TT / 128);
    sgemm_kernel<<<gD, 256>>>(xn, wq, q, TT, DD, DD, nullptr, nullptr, 0);
    sgemm_kernel<<<gD, 256>>>(xn, wk, k, TT, DD, DD, nullptr, nullptr, 0);
    sgemm_kernel<<<gD, 256>>>(xn, wv, v, TT, DD, DD, nullptr, nullptr, 0);

    rope_kernel<<<(TT * HH * 32) / 256, 256>>>(q, k);

    attn_kernel<<<dim3(TT / 64, HH), 256, ATTN_SMEM>>>(q, k, v, ctx);

    // out = ctx @ wo + x
    sgemm_kernel<<<gD, 256>>>(ctx, wo, out, TT, DD, DD, nullptr, x, 2);
    // ffh = gelu(xn @ w1 + b1)
    sgemm_kernel<<<dim3(FFD / 128, TT / 128), 256>>>(xn, w1, ffh, TT, FFD, DD, b1, nullptr, 1);
    // out += ffh @ w2 + b2
    sgemm_kernel<<<gD, 256>>>(ffh, w2, out, TT, DD, FFD, b2, nullptr, 3);
}

// round 3
// speedup vs baseline: 1.2342x; 1.2342x over previous
#include <cuda_runtime.h>
#include <cuda_fp16.h>
#include <cstdint>
#include <math.h>

#define TT 2048
#define DD 2048
#define HH 16
#define DHD 128
#define FFD 8192

// ---------------- scratch (device globals) ---------------------------------
__device__ __align__(256) __half g_xn [TT * DD];
__device__ __align__(256) float  g_q[TT * DD], g_k[TT * DD], g_v[TT * DD];
__device__ __align__(256) __half g_ctx[TT * DD];
__device__ __align__(256) __half g_ffh[TT * FFD];
__device__ __align__(256) __half g_wqt[DD * DD];
__device__ __align__(256) __half g_wkt[DD * DD];
__device__ __align__(256) __half g_wvt[DD * DD];
__device__ __align__(256) __half g_wot[DD * DD];
__device__ __align__(256) __half g_w1t[DD * FFD];
__device__ __align__(256) __half g_w2t[FFD * DD];

// ---------------- PTX helpers ----------------------------------------------
__device__ __forceinline__ uint32_t smem_u32(const void* p) {
    uint32_t a;
    asm("{ .reg .u64 t; cvta.to.shared.u64 t, %1; cvt.u32.u64 %0, t; }"
        : "=r"(a) : "l"(p));
    return a;
}
__device__ __forceinline__ void cpa16(uint32_t dst, const void* src) {
    asm volatile("cp.async.cg.shared.global [%0], [%1], 16;"
                 :: "r"(dst), "l"(src));
}
#define CPA_COMMIT() asm volatile("cp.async.commit_group;" ::: "memory")
#define CPA_WAIT1()  asm volatile("cp.async.wait_group 1;" ::: "memory")
#define CPA_WAIT0()  asm volatile("cp.async.wait_group 0;" ::: "memory")

__device__ __forceinline__ void ldsm4(uint32_t& r0, uint32_t& r1,
                                      uint32_t& r2, uint32_t& r3, uint32_t a) {
    asm volatile("ldmatrix.sync.aligned.m8n8.x4.shared.b16 {%0,%1,%2,%3}, [%4];"
                 : "=r"(r0), "=r"(r1), "=r"(r2), "=r"(r3) : "r"(a));
}
__device__ __forceinline__ void mma16816(float* c, const uint32_t* a,
                                         const uint32_t* b) {
    asm volatile(
        "mma.sync.aligned.m16n8k16.row.col.f32.f16.f16.f32 "
        "{%0,%1,%2,%3}, {%4,%5,%6,%7}, {%8,%9}, {%0,%1,%2,%3};"
        : "+f"(c[0]), "+f"(c[1]), "+f"(c[2]), "+f"(c[3])
        : "r"(a[0]), "r"(a[1]), "r"(a[2]), "r"(a[3]), "r"(b[0]), "r"(b[1]));
}

__device__ __forceinline__ float gelu_tanh(float v) {
    float u = 0.7978845608028654f * (v + 0.044715f * v * v * v);
    return 0.5f * v * (1.0f + tanhf(u));
}

// ---------------- LayerNorm -> fp16 ----------------------------------------
__global__ void layernorm_kernel(const float* __restrict__ x,
                                 const float* __restrict__ scale,
                                 const float* __restrict__ offset,
                                 __half* __restrict__ xn) {
    int row = blockIdx.x;
    int tid = threadIdx.x;
    const float* xr = x + (size_t)row * DD;
    float vals[8];
    float s = 0.f;
#pragma unroll
    for (int i = 0; i < 8; i++) { vals[i] = xr[tid + i * 256]; s += vals[i]; }
    __shared__ float red[256];
    red[tid] = s; __syncthreads();
#pragma unroll
    for (int off = 128; off > 0; off >>= 1) {
        if (tid < off) red[tid] += red[tid + off];
        __syncthreads();
    }
    float mean = red[0] * (1.0f / DD);
    __syncthreads();
    float vs = 0.f;
#pragma unroll
    for (int i = 0; i < 8; i++) { float d = vals[i] - mean; vs += d * d; }
    red[tid] = vs; __syncthreads();
#pragma unroll
    for (int off = 128; off > 0; off >>= 1) {
        if (tid < off) red[tid] += red[tid + off];
        __syncthreads();
    }
    float var = red[0] * (1.0f / DD);
    float inv = rsqrtf(var + 1e-5f);
#pragma unroll
    for (int i = 0; i < 8; i++) {
        int c = tid + i * 256;
        float y = scale[c] * inv * (vals[i] - mean) + offset[c];
        xn[(size_t)row * DD + c] = __float2half(y);
    }
}

// ---------------- weight transpose: W[K,N] -> Wt[N,K] fp16 -----------------
__global__ void transpose_half(const float* __restrict__ W,
                               __half* __restrict__ T_,
                               int K, int N) {
    __shared__ float t[32][33];
    int n0 = blockIdx.x * 32, k0 = blockIdx.y * 32;
    int tx = threadIdx.x, ty = threadIdx.y;  // 32 x 8
#pragma unroll
    for (int i = 0; i < 32; i += 8)
        t[ty + i][tx] = W[(size_t)(k0 + ty + i) * N + n0 + tx];
    __syncthreads();
#pragma unroll
    for (int i = 0; i < 32; i += 8)
        T_[(size_t)(n0 + ty + i) * K + k0 + tx] = __float2half(t[tx][ty + i]);
}

// ---------------- RoPE ------------------------------------------------------
__global__ void rope_kernel(float* __restrict__ q, float* __restrict__ k) {
    int idx = blockIdx.x * blockDim.x + threadIdx.x;
    int j = idx & 31;
    int h = (idx >> 5) & 15;
    int t = idx >> 9;
    float inv = (float)pow(10000.0, -(double)(2 * j) / 64.0);
    float ang = (float)t * inv;
    float c = cosf(ang), s = sinf(ang);
    int base = t * DD + h * DHD + 2 * j;
    float qe = q[base], qo = q[base + 1];
    q[base]     = qe * c - qo * s;
    q[base + 1] = qo * c + qe * s;
    float ke = k[base], ko = k[base + 1];
    k[base]     = ke * c - ko * s;
    k[base + 1] = ko * c + ke * s;
}

// ---------------- HMMA GEMM: 128x128 tile, fp16 in / fp32 acc --------------
// C[M,N] = A[M,K] @ W[K,N]; A fp16 [M,K] row-major; W pre-transposed fp16 [N,K]
// mode 0: outF = D           mode 1: outH = fp16(gelu(D + bias))
// mode 2: outF = D + res     mode 3: outF += D + bias
#define RB 80                  // smem row bytes (32 halfs + 8 pad)
#define TILEB (128 * RB)       // 10240 B per tile
#define STAGEB (2 * TILEB)     // A + B per stage
#define GSMEM (2 * STAGEB)     // 2 stages = 40960 B

__global__ void __launch_bounds__(256, 2) gemm_hmma(
    const __half* __restrict__ A, const __half* __restrict__ B,
    int M, int N, int K,
    float* __restrict__ outF, __half* __restrict__ outH,
    const float* __restrict__ bias, const float* __restrict__ res, int mode) {
    extern __shared__ char smem[];
    const uint32_t sb = smem_u32(smem);

    const int tid = threadIdx.x;
    const int wid = tid >> 5, lane = tid & 31;
    const int wm = wid >> 2, wn = wid & 3;      // warp tile: 64 x 32
    const int m0 = blockIdx.y << 7, n0 = blockIdx.x << 7;

    // per-thread copy indices (2 chunks of A, 2 of B per stage)
    const int cr0 = tid >> 2, cq0 = tid & 3;          // rows 0..63
    const int cr1 = cr0 + 64;

    // ldmatrix base offsets
    const uint32_t a_off = (uint32_t)(wm * 64 + (lane & 15)) * RB + ((lane >> 4) << 4);
    const uint32_t b_off = (uint32_t)(wn * 32 + (lane & 7) + ((lane >> 4) << 3)) * RB
                         + (((lane >> 3) & 1) << 4);

    float acc[4][4][4];
#pragma unroll
    for (int i = 0; i < 4; i++)
#pragma unroll
        for (int j = 0; j < 4; j++)
#pragma unroll
            for (int r = 0; r < 4; r++) acc[i][j][r] = 0.f;

    const int nch = K >> 5;

    // preload stage 0
    {
        const __half* Ap = A + (size_t)m0 * K + cq0 * 8;
        const __half* Bp = B + (size_t)n0 * K + cq0 * 8;
        cpa16(sb + cr0 * RB + cq0 * 16,         Ap + (size_t)cr0 * K);
        cpa16(sb + cr1 * RB + cq0 * 16,         Ap + (size_t)cr1 * K);
        cpa16(sb + TILEB + cr0 * RB + cq0 * 16, Bp + (size_t)cr0 * K);
        cpa16(sb + TILEB + cr1 * RB + cq0 * 16, Bp + (size_t)cr1 * K);
        CPA_COMMIT();
    }

    for (int i = 0; i < nch; i++) {
        if (i + 1 < nch) {
            const uint32_t st = sb + ((i + 1) & 1) * STAGEB;
            int kc = (i + 1) << 5;
            const __half* Ap = A + (size_t)m0 * K + kc + cq0 * 8;
            const __half* Bp = B + (size_t)n0 * K + kc + cq0 * 8;
            cpa16(st + cr0 * RB + cq0 * 16,         Ap + (size_t)cr0 * K);
            cpa16(st + cr1 * RB + cq0 * 16,         Ap + (size_t)cr1 * K);
            cpa16(st + TILEB + cr0 * RB + cq0 * 16, Bp + (size_t)cr0 * K);
            cpa16(st + TILEB + cr1 * RB + cq0 * 16, Bp + (size_t)cr1 * K);
            CPA_COMMIT();
            CPA_WAIT1();
        } else {
            CPA_WAIT0();
        }
        __syncthreads();

        const uint32_t sA = sb + (i & 1) * STAGEB;
        const uint32_t sB = sA + TILEB;
#pragma unroll
        for (int ks = 0; ks < 2; ks++) {
            uint32_t a[4][4];
#pragma unroll
            for (int fi = 0; fi < 4; fi++)
                ldsm4(a[fi][0], a[fi][1], a[fi][2], a[fi][3],
                      sA + a_off + fi * 16 * RB + ks * 32);
            uint32_t b[4][2];
#pragma unroll
            for (int j2 = 0; j2 < 2; j2++) {
                uint32_t r0, r1, r2, r3;
                ldsm4(r0, r1, r2, r3, sB + b_off + j2 * 16 * RB + ks * 32);
                b[j2 * 2][0] = r0; b[j2 * 2][1] = r1;
                b[j2 * 2 + 1][0] = r2; b[j2 * 2 + 1][1] = r3;
            }
#pragma unroll
            for (int fi = 0; fi < 4; fi++)
#pragma unroll
                for (int j = 0; j < 4; j++)
                    mma16816(acc[fi][j], a[fi], b[j]);
        }
        __syncthreads();
    }

    // epilogue
    const int r_base = m0 + wm * 64 + (lane >> 2);
    const int c_base = n0 + wn * 32 + (lane & 3) * 2;
#pragma unroll
    for (int fi = 0; fi < 4; fi++) {
#pragma unroll
        for (int j = 0; j < 4; j++) {
            int row = r_base + fi * 16;
            int col = c_base + j * 8;
#pragma unroll
            for (int half_ = 0; half_ < 2; half_++) {
                int r = row + half_ * 8;
                float v0 = acc[fi][j][half_ * 2 + 0];
                float v1 = acc[fi][j][half_ * 2 + 1];
                size_t o = (size_t)r * N + col;
                if (mode == 0) {
                    outF[o] = v0; outF[o + 1] = v1;
                } else if (mode == 2) {
                    outF[o] = v0 + res[o]; outF[o + 1] = v1 + res[o + 1];
                } else if (mode == 1) {
                    outH[o]     = __float2half(gelu_tanh(v0 + bias[col]));
                    outH[o + 1] = __float2half(gelu_tanh(v1 + bias[col + 1]));
                } else {
                    outF[o]     += v0 + bias[col];
                    outF[o + 1] += v1 + bias[col + 1];
                }
            }
        }
    }
}

// ---------------- Flash attention (causal, fp32, 64x64 tiles) --------------
#define KP 129
#define SP 65
#define ATTN_SMEM ((64 * 128 + 64 * 128 + 64 * KP + 64 * SP) * 4)

__global__ void attn_kernel(const float* __restrict__ q,
                            const float* __restrict__ k,
                            const float* __restrict__ v,
                            __half* __restrict__ ctx) {
    extern __shared__ float sm[];
    float* Qs = sm;
    float* Vs = Qs + 64 * 128;
    float* Ks = Vs + 64 * 128;
    float* Ss = Ks + 64 * KP;

    int qt = blockIdx.x, h = blockIdx.y;
    int tid = threadIdx.x;
    int q0 = qt * 64;

    for (int i = tid; i < 64 * 32; i += 256) {
        int r = i >> 5, c4 = (i & 31) << 2;
        *(float4*)&Qs[r * 128 + c4] =
            *(const float4*)&q[(size_t)(q0 + r) * DD + h * DHD + c4];
    }

    const int orow = tid >> 2;
    const int oc0  = (tid & 3) << 5;
    const int sr   = (tid >> 4) << 2;
    const int sc   = (tid & 15) << 2;
    const int pc0  = (tid & 3) << 4;

    float O[32];
#pragma unroll
    for (int i = 0; i < 32; i++) O[i] = 0.f;
    float m_prev = -1e30f, l = 0.f;
    const float sm_scale = 0.08838834764831845f;

    for (int kt = 0; kt <= qt; kt++) {
        __syncthreads();
        for (int i = tid; i < 64 * 32; i += 256) {
            int r = i >> 5, c4 = (i & 31) << 2;
            size_t g = (size_t)(kt * 64 + r) * DD + h * DHD + c4;
            float4 kv = *(const float4*)&k[g];
            Ks[r * KP + c4 + 0] = kv.x;
            Ks[r * KP + c4 + 1] = kv.y;
            Ks[r * KP + c4 + 2] = kv.z;
            Ks[r * KP + c4 + 3] = kv.w;
            *(float4*)&Vs[r * 128 + c4] = *(const float4*)&v[g];
        }
        __syncthreads();

        float acc[4][4];
#pragma unroll
        for (int i = 0; i < 4; i++)
#pragma unroll
            for (int j = 0; j < 4; j++) acc[i][j] = 0.f;
        for (int c = 0; c < 128; c++) {
            float qa[4], kb[4];
#pragma unroll
            for (int i = 0; i < 4; i++) qa[i] = Qs[(sr + i) * 128 + c];
#pragma unroll
            for (int j = 0; j < 4; j++) kb[j] = Ks[(sc + j) * KP + c];
#pragma unroll
            for (int i = 0; i < 4; i++)
#pragma unroll
                for (int j = 0; j < 4; j++) acc[i][j] += qa[i] * kb[j];
        }
        bool diag = (kt == qt);
#pragma unroll
        for (int i = 0; i < 4; i++)
#pragma unroll
            for (int j = 0; j < 4; j++) {
                float sv = acc[i][j] * sm_scale;
                if (diag && (kt * 64 + sc + j > q0 + sr + i)) sv = -1e9f;
                Ss[(sr + i) * SP + sc + j] = sv;
            }
        __syncthreads();

        float mloc = -1e30f;
#pragma unroll
        for (int c = 0; c < 16; c++)
            mloc = fmaxf(mloc, Ss[orow * SP + pc0 + c]);
        mloc = fmaxf(mloc, __shfl_xor_sync(0xffffffffu, mloc, 1));
        mloc = fmaxf(mloc, __shfl_xor_sync(0xffffffffu, mloc, 2));
        float m_new = fmaxf(m_prev, mloc);
        float corr = __expf(m_prev - m_new);
        float psum = 0.f;
#pragma unroll
        for (int c = 0; c < 16; c++) {
            float p = __expf(Ss[orow * SP + pc0 + c] - m_new);
            Ss[orow * SP + pc0 + c] = p;
            psum += p;
        }
        psum += __shfl_xor_sync(0xffffffffu, psum, 1);
        psum += __shfl_xor_sync(0xffffffffu, psum, 2);
        l = l * corr + psum;
        m_prev = m_new;
#pragma unroll
        for (int i = 0; i < 32; i++) O[i] *= corr;
        __syncthreads();

#pragma unroll 4
        for (int j = 0; j < 64; j++) {
            float p = Ss[orow * SP + j];
            const float4* vv = (const float4*)&Vs[j * 128 + oc0];
#pragma unroll
            for (int cc = 0; cc < 8; cc++) {
                float4 v4 = vv[cc];
                O[cc * 4 + 0] += p * v4.x;
                O[cc * 4 + 1] += p * v4.y;
                O[cc * 4 + 2] += p * v4.z;
                O[cc * 4 + 3] += p * v4.w;
            }
        }
    }

    float invl = 1.0f / l;
    size_t dst = (size_t)(q0 + orow) * DD + h * DHD + oc0;
#pragma unroll
    for (int i = 0; i < 32; i++)
        ctx[dst + i] = __float2half(O[i] * invl);
}

// ---------------- launch ----------------------------------------------------
extern "C" void kernel_launch(void* const* d_in, const int* in_sizes, int n_in,
                              void* d_out, int out_size) {
    const float* x      = (const float*)d_in[0];
    const float* scale  = (const float*)d_in[2];
    const float* offset = (const float*)d_in[3];
    const float* wq     = (const float*)d_in[4];
    const float* wk     = (const float*)d_in[5];
    const float* wv     = (const float*)d_in[6];
    const float* wo     = (const float*)d_in[7];
    const float* w1     = (const float*)d_in[8];
    const float* b1     = (const float*)d_in[9];
    const float* w2     = (const float*)d_in[10];
    const float* b2     = (const float*)d_in[11];
    float* out = (float*)d_out;

    __half *xn, *ctx, *ffh, *wqt, *wkt, *wvt, *wot, *w1t, *w2t;
    float *q, *k, *v;
    cudaGetSymbolAddress((void**)&xn, g_xn);
    cudaGetSymbolAddress((void**)&q, g_q);
    cudaGetSymbolAddress((void**)&k, g_k);
    cudaGetSymbolAddress((void**)&v, g_v);
    cudaGetSymbolAddress((void**)&ctx, g_ctx);
    cudaGetSymbolAddress((void**)&ffh, g_ffh);
    cudaGetSymbolAddress((void**)&wqt, g_wqt);
    cudaGetSymbolAddress((void**)&wkt, g_wkt);
    cudaGetSymbolAddress((void**)&wvt, g_wvt);
    cudaGetSymbolAddress((void**)&wot, g_wot);
    cudaGetSymbolAddress((void**)&w1t, g_w1t);
    cudaGetSymbolAddress((void**)&w2t, g_w2t);

    cudaFuncSetAttribute(attn_kernel,
                         cudaFuncAttributeMaxDynamicSharedMemorySize, ATTN_SMEM);

    dim3 tb(32, 8);
    transpose_half<<<dim3(DD / 32, DD / 32), tb>>>(wq, wqt, DD, DD);
    transpose_half<<<dim3(DD / 32, DD / 32), tb>>>(wk, wkt, DD, DD);
    transpose_half<<<dim3(DD / 32, DD / 32), tb>>>(wv, wvt, DD, DD);
    transpose_half<<<dim3(DD / 32, DD / 32), tb>>>(wo, wot, DD, DD);
    transpose_half<<<dim3(FFD / 32, DD / 32), tb>>>(w1, w1t, DD, FFD);
    transpose_half<<<dim3(DD / 32, FFD / 32), tb>>>(w2, w2t, FFD, DD);

    layernorm_kernel<<<TT, 256>>>(x, scale, offset, xn);

    dim3 gD(DD / 128, TT / 128);
    gemm_hmma<<<gD, 256, GSMEM>>>(xn, wqt, TT, DD, DD, q, nullptr, nullptr, nullptr, 0);
    gemm_hmma<<<gD, 256, GSMEM>>>(xn, wkt, TT, DD, DD, k, nullptr, nullptr, nullptr, 0);
    gemm_hmma<<<gD, 256, GSMEM>>>(xn, wvt, TT, DD, DD, v, nullptr, nullptr, nullptr, 0);

    rope_kernel<<<(TT * HH * 32) / 256, 256>>>(q, k);

    attn_kernel<<<dim3(TT / 64, HH), 256, ATTN_SMEM>>>(q, k, v, ctx);

    // out = ctx @ wo + x
    gemm_hmma<<<gD, 256, GSMEM>>>(ctx, wot, TT, DD, DD, out, nullptr, nullptr, x, 2);
    // ffh = fp16(gelu(xn @ w1 + b1))
    gemm_hmma<<<dim3(FFD / 128, TT / 128), 256, GSMEM>>>(xn, w1t, TT, FFD, DD,
                                                         nullptr, ffh, b1, nullptr, 1);
    // out += ffh @ w2 + b2
    gemm_hmma<<<gD, 256, GSMEM>>>(ffh, w2t, TT, DD, FFD, out, nullptr, b2, nullptr, 3);
}

// round 5
// speedup vs baseline: 7.5782x; 6.1404x over previous
#include <cuda_runtime.h>
#include <cuda_fp16.h>
#include <cstdint>
#include <math.h>

#define TT 2048
#define DD 2048
#define HH 16
#define DHD 128
#define FFD 8192

// ---------------- scratch (device globals) ---------------------------------
__device__ __align__(256) __half g_xn [TT * DD];
__device__ __align__(256) float  g_q[TT * DD], g_k[TT * DD], g_v[TT * DD];
__device__ __align__(256) __half g_qh[TT * DD], g_kh[TT * DD], g_vt[TT * DD];
__device__ __align__(256) __half g_ctx[TT * DD];
__device__ __align__(256) __half g_ffh[TT * FFD];
__device__ __align__(256) __half g_wqt[DD * DD];
__device__ __align__(256) __half g_wkt[DD * DD];
__device__ __align__(256) __half g_wvt[DD * DD];
__device__ __align__(256) __half g_wot[DD * DD];
__device__ __align__(256) __half g_w1t[DD * FFD];
__device__ __align__(256) __half g_w2t[FFD * DD];

// ---------------- PTX helpers ----------------------------------------------
__device__ __forceinline__ uint32_t smem_u32(const void* p) {
    uint32_t a;
    asm("{ .reg .u64 t; cvta.to.shared.u64 t, %1; cvt.u32.u64 %0, t; }"
        : "=r"(a) : "l"(p));
    return a;
}
__device__ __forceinline__ uint32_t h2_as_u32(__half2 h) {
    union { __half2 h2; uint32_t u; } cvt;
    cvt.h2 = h;
    return cvt.u;
}
__device__ __forceinline__ void cpa16(uint32_t dst, const void* src) {
    asm volatile("cp.async.cg.shared.global [%0], [%1], 16;"
                 :: "r"(dst), "l"(src));
}
#define CPA_COMMIT() asm volatile("cp.async.commit_group;" ::: "memory")
#define CPA_WAIT1()  asm volatile("cp.async.wait_group 1;" ::: "memory")
#define CPA_WAIT0()  asm volatile("cp.async.wait_group 0;" ::: "memory")

__device__ __forceinline__ void ldsm4(uint32_t& r0, uint32_t& r1,
                                      uint32_t& r2, uint32_t& r3, uint32_t a) {
    asm volatile("ldmatrix.sync.aligned.m8n8.x4.shared.b16 {%0,%1,%2,%3}, [%4];"
                 : "=r"(r0), "=r"(r1), "=r"(r2), "=r"(r3) : "r"(a));
}
__device__ __forceinline__ void mma16816(float* c, const uint32_t* a,
                                         const uint32_t* b) {
    asm volatile(
        "mma.sync.aligned.m16n8k16.row.col.f32.f16.f16.f32 "
        "{%0,%1,%2,%3}, {%4,%5,%6,%7}, {%8,%9}, {%0,%1,%2,%3};"
        : "+f"(c[0]), "+f"(c[1]), "+f"(c[2]), "+f"(c[3])
        : "r"(a[0]), "r"(a[1]), "r"(a[2]), "r"(a[3]), "r"(b[0]), "r"(b[1]));
}

__device__ __forceinline__ float gelu_tanh(float v) {
    float u = 0.7978845608028654f * (v + 0.044715f * v * v * v);
    return 0.5f * v * (1.0f + tanhf(u));
}

// ---------------- LayerNorm -> fp16 ----------------------------------------
__global__ void layernorm_kernel(const float* __restrict__ x,
                                 const float* __restrict__ scale,
                                 const float* __restrict__ offset,
                                 __half* __restrict__ xn) {
    int row = blockIdx.x;
    int tid = threadIdx.x;
    const float* xr = x + (size_t)row * DD;
    float vals[8];
    float s = 0.f;
#pragma unroll
    for (int i = 0; i < 8; i++) { vals[i] = xr[tid + i * 256]; s += vals[i]; }
    __shared__ float red[256];
    red[tid] = s; __syncthreads();
#pragma unroll
    for (int off = 128; off > 0; off >>= 1) {
        if (tid < off) red[tid] += red[tid + off];
        __syncthreads();
    }
    float mean = red[0] * (1.0f / DD);
    __syncthreads();
    float vs = 0.f;
#pragma unroll
    for (int i = 0; i < 8; i++) { float d = vals[i] - mean; vs += d * d; }
    red[tid] = vs; __syncthreads();
#pragma unroll
    for (int off = 128; off > 0; off >>= 1) {
        if (tid < off) red[tid] += red[tid + off];
        __syncthreads();
    }
    float var = red[0] * (1.0f / DD);
    float inv = rsqrtf(var + 1e-5f);
#pragma unroll
    for (int i = 0; i < 8; i++) {
        int c = tid + i * 256;
        float y = scale[c] * inv * (vals[i] - mean) + offset[c];
        xn[(size_t)row * DD + c] = __float2half(y);
    }
}

// ---------------- weight transpose: W[K,N] -> Wt[N,K] fp16 -----------------
__global__ void transpose_half(const float* __restrict__ W,
                               __half* __restrict__ T_,
                               int K, int N) {
    __shared__ float t[32][33];
    int n0 = blockIdx.x * 32, k0 = blockIdx.y * 32;
    int tx = threadIdx.x, ty = threadIdx.y;  // 32 x 8
#pragma unroll
    for (int i = 0; i < 32; i += 8)
        t[ty + i][tx] = W[(size_t)(k0 + ty + i) * N + n0 + tx];
    __syncthreads();
#pragma unroll
    for (int i = 0; i < 32; i += 8)
        T_[(size_t)(n0 + ty + i) * K + k0 + tx] = __float2half(t[tx][ty + i]);
}

// ---------------- v fp32 [T][D] -> vt fp16 [D][T] --------------------------
__global__ void transpose_vt(const float* __restrict__ v,
                             __half* __restrict__ vt) {
    __shared__ float t[32][33];
    int d0 = blockIdx.x * 32, t0 = blockIdx.y * 32;
    int tx = threadIdx.x, ty = threadIdx.y;  // 32 x 8
#pragma unroll
    for (int i = 0; i < 32; i += 8)
        t[ty + i][tx] = v[(size_t)(t0 + ty + i) * DD + d0 + tx];
    __syncthreads();
#pragma unroll
    for (int i = 0; i < 32; i += 8)
        vt[(size_t)(d0 + ty + i) * TT + t0 + tx] = __float2half(t[tx][ty + i]);
}

// ---------------- RoPE (fp32 in) -> fp16 q,k --------------------------------
__global__ void rope_half(const float* __restrict__ q,
                          const float* __restrict__ k,
                          __half* __restrict__ qh, __half* __restrict__ kh) {
    int idx = blockIdx.x * blockDim.x + threadIdx.x;  // T*H*64
    int j = idx & 63;
    int h = (idx >> 6) & 15;
    int t = idx >> 10;
    int base = t * DD + h * DHD;
    if (j < 32) {
        float inv = (float)pow(10000.0, -(double)(2 * j) / 64.0);
        float ang = (float)t * inv;
        float c = cosf(ang), s = sinf(ang);
        int o = base + 2 * j;
        float qe = q[o], qo_ = q[o + 1];
        qh[o]     = __float2half(qe * c - qo_ * s);
        qh[o + 1] = __float2half(qo_ * c + qe * s);
        float ke = k[o], ko = k[o + 1];
        kh[o]     = __float2half(ke * c - ko * s);
        kh[o + 1] = __float2half(ko * c + ke * s);
    } else {
        int o = base + 64 + 2 * (j - 32);
        qh[o]     = __float2half(q[o]);
        qh[o + 1] = __float2half(q[o + 1]);
        kh[o]     = __float2half(k[o]);
        kh[o + 1] = __float2half(k[o + 1]);
    }
}

// ---------------- HMMA GEMM: 128x128 tile, fp16 in / fp32 acc --------------
#define RB 80
#define TILEB (128 * RB)
#define STAGEB (2 * TILEB)
#define GSMEM (2 * STAGEB)

__global__ void __launch_bounds__(256, 2) gemm_hmma(
    const __half* __restrict__ A, const __half* __restrict__ B,
    int M, int N, int K,
    float* __restrict__ outF, __half* __restrict__ outH,
    const float* __restrict__ bias, const float* __restrict__ res, int mode) {
    extern __shared__ char smem[];
    const uint32_t sb = smem_u32(smem);

    const int tid = threadIdx.x;
    const int wid = tid >> 5, lane = tid & 31;
    const int wm = wid >> 2, wn = wid & 3;
    const int m0 = blockIdx.y << 7, n0 = blockIdx.x << 7;

    const int cr0 = tid >> 2, cq0 = tid & 3;
    const int cr1 = cr0 + 64;

    const uint32_t a_off = (uint32_t)(wm * 64 + (lane & 15)) * RB + ((lane >> 4) << 4);
    const uint32_t b_off = (uint32_t)(wn * 32 + (lane & 7) + ((lane >> 4) << 3)) * RB
                         + (((lane >> 3) & 1) << 4);

    float acc[4][4][4];
#pragma unroll
    for (int i = 0; i < 4; i++)
#pragma unroll
        for (int j = 0; j < 4; j++)
#pragma unroll
            for (int r = 0; r < 4; r++) acc[i][j][r] = 0.f;

    const int nch = K >> 5;

    {
        const __half* Ap = A + (size_t)m0 * K + cq0 * 8;
        const __half* Bp = B + (size_t)n0 * K + cq0 * 8;
        cpa16(sb + cr0 * RB + cq0 * 16,         Ap + (size_t)cr0 * K);
        cpa16(sb + cr1 * RB + cq0 * 16,         Ap + (size_t)cr1 * K);
        cpa16(sb + TILEB + cr0 * RB + cq0 * 16, Bp + (size_t)cr0 * K);
        cpa16(sb + TILEB + cr1 * RB + cq0 * 16, Bp + (size_t)cr1 * K);
        CPA_COMMIT();
    }

    for (int i = 0; i < nch; i++) {
        if (i + 1 < nch) {
            const uint32_t st = sb + ((i + 1) & 1) * STAGEB;
            int kc = (i + 1) << 5;
            const __half* Ap = A + (size_t)m0 * K + kc + cq0 * 8;
            const __half* Bp = B + (size_t)n0 * K + kc + cq0 * 8;
            cpa16(st + cr0 * RB + cq0 * 16,         Ap + (size_t)cr0 * K);
            cpa16(st + cr1 * RB + cq0 * 16,         Ap + (size_t)cr1 * K);
            cpa16(st + TILEB + cr0 * RB + cq0 * 16, Bp + (size_t)cr0 * K);
            cpa16(st + TILEB + cr1 * RB + cq0 * 16, Bp + (size_t)cr1 * K);
            CPA_COMMIT();
            CPA_WAIT1();
        } else {
            CPA_WAIT0();
        }
        __syncthreads();

        const uint32_t sA = sb + (i & 1) * STAGEB;
        const uint32_t sB = sA + TILEB;
#pragma unroll
        for (int ks = 0; ks < 2; ks++) {
            uint32_t a[4][4];
#pragma unroll
            for (int fi = 0; fi < 4; fi++)
                ldsm4(a[fi][0], a[fi][1], a[fi][2], a[fi][3],
                      sA + a_off + fi * 16 * RB + ks * 32);
            uint32_t b[4][2];
#pragma unroll
            for (int j2 = 0; j2 < 2; j2++) {
                uint32_t r0, r1, r2, r3;
                ldsm4(r0, r1, r2, r3, sB + b_off + j2 * 16 * RB + ks * 32);
                b[j2 * 2][0] = r0; b[j2 * 2][1] = r1;
                b[j2 * 2 + 1][0] = r2; b[j2 * 2 + 1][1] = r3;
            }
#pragma unroll
            for (int fi = 0; fi < 4; fi++)
#pragma unroll
                for (int j = 0; j < 4; j++)
                    mma16816(acc[fi][j], a[fi], b[j]);
        }
        __syncthreads();
    }

    const int r_base = m0 + wm * 64 + (lane >> 2);
    const int c_base = n0 + wn * 32 + (lane & 3) * 2;
#pragma unroll
    for (int fi = 0; fi < 4; fi++) {
#pragma unroll
        for (int j = 0; j < 4; j++) {
            int row = r_base + fi * 16;
            int col = c_base + j * 8;
#pragma unroll
            for (int half_ = 0; half_ < 2; half_++) {
                int r = row + half_ * 8;
                float v0 = acc[fi][j][half_ * 2 + 0];
                float v1 = acc[fi][j][half_ * 2 + 1];
                size_t o = (size_t)r * N + col;
                if (mode == 0) {
                    outF[o] = v0; outF[o + 1] = v1;
                } else if (mode == 2) {
                    outF[o] = v0 + res[o]; outF[o + 1] = v1 + res[o + 1];
                } else if (mode == 1) {
                    outH[o]     = __float2half(gelu_tanh(v0 + bias[col]));
                    outH[o + 1] = __float2half(gelu_tanh(v1 + bias[col + 1]));
                } else {
                    outF[o]     += v0 + bias[col];
                    outF[o + 1] += v1 + bias[col + 1];
                }
            }
        }
    }
}

// ---------------- Flash attention on mma.sync -------------------------------
// Br=128 (8 warps x 16 rows), Bc=64, DH=128
#define KRB 272                       // K tile row bytes (128 halfs + 16 pad)
#define VRB 144                       // Vt tile row bytes (64 halfs + 16 pad)
#define KSTG (64 * KRB)               // 17408
#define SSTG (KSTG + 128 * VRB)       // 35840
#define ASMEM (2 * SSTG)              // 71680

__global__ void __launch_bounds__(256, 1) attn_mma(
    const __half* __restrict__ qh, const __half* __restrict__ kh,
    const __half* __restrict__ vt, __half* __restrict__ ctx) {
    extern __shared__ char smem[];
    const uint32_t sb = smem_u32(smem);
    const int tid = threadIdx.x, w = tid >> 5, lane = tid & 31;
    const int qt = blockIdx.x, h = blockIdx.y;
    const int q0 = qt * 128;
    const int hbase = h * DHD;
    const int nkt = 2 * qt + 2;

    // ---- load Q tile [128][128] into smem, extract A-frags ----
#pragma unroll
    for (int p = 0; p < 8; p++) {
        int idx = tid + p * 256;
        int row = idx >> 4, c = idx & 15;
        cpa16(sb + row * KRB + c * 16,
              qh + (size_t)(q0 + row) * DD + hbase + c * 8);
    }
    CPA_COMMIT(); CPA_WAIT0(); __syncthreads();
    uint32_t qf[8][4];
    {
        uint32_t aoff = (uint32_t)(w * 16 + (lane & 15)) * KRB + ((lane >> 4) << 4);
#pragma unroll
        for (int ks = 0; ks < 8; ks++)
            ldsm4(qf[ks][0], qf[ks][1], qf[ks][2], qf[ks][3],
                  sb + aoff + ks * 32);
    }
    __syncthreads();

    float O[16][4];
#pragma unroll
    for (int j = 0; j < 16; j++)
#pragma unroll
        for (int r = 0; r < 4; r++) O[j][r] = 0.f;
    float m0 = -1e30f, m1 = -1e30f, l0 = 0.f, l1 = 0.f;

    // ---- preload kt=0 ----
    {
        int kv0 = 0;
        uint32_t base = sb;
#pragma unroll
        for (int p = 0; p < 4; p++) {
            int idx = tid + p * 256;
            int row = idx >> 4, c = idx & 15;
            cpa16(base + row * KRB + c * 16,
                  kh + (size_t)(kv0 + row) * DD + hbase + c * 8);
        }
#pragma unroll
        for (int p = 0; p < 4; p++) {
            int idx = tid + p * 256;
            int row = idx >> 3, c = idx & 7;
            cpa16(base + KSTG + row * VRB + c * 16,
                  vt + (size_t)(hbase + row) * TT + kv0 + c * 8);
        }
        CPA_COMMIT();
    }

    const float sm_scale = 0.08838834764831845f;  // 1/sqrt(128)
    const int r0g = q0 + w * 16 + (lane >> 2);

    for (int kt = 0; kt < nkt; kt++) {
        if (kt + 1 < nkt) {
            int kv0 = (kt + 1) * 64;
            uint32_t base = sb + ((kt + 1) & 1) * SSTG;
#pragma unroll
            for (int p = 0; p < 4; p++) {
                int idx = tid + p * 256;
                int row = idx >> 4, c = idx & 15;
                cpa16(base + row * KRB + c * 16,
                      kh + (size_t)(kv0 + row) * DD + hbase + c * 8);
            }
#pragma unroll
            for (int p = 0; p < 4; p++) {
                int idx = tid + p * 256;
                int row = idx >> 3, c = idx & 7;
                cpa16(base + KSTG + row * VRB + c * 16,
                      vt + (size_t)(hbase + row) * TT + kv0 + c * 8);
            }
            CPA_COMMIT();
            CPA_WAIT1();
        } else {
            CPA_WAIT0();
        }
        __syncthreads();

        const uint32_t cur = sb + (kt & 1) * SSTG;

        // ---- S = Q K^T ----
        float S[8][4];
#pragma unroll
        for (int j = 0; j < 8; j++)
#pragma unroll
            for (int r = 0; r < 4; r++) S[j][r] = 0.f;
        {
            uint32_t bko = (uint32_t)((lane & 7) + ((lane >> 4) << 3)) * KRB
                         + (((lane >> 3) & 1) << 4);
#pragma unroll
            for (int j2 = 0; j2 < 4; j2++) {
                uint32_t bbase = cur + bko + j2 * 16 * KRB;
#pragma unroll
                for (int ks = 0; ks < 8; ks++) {
                    uint32_t r0, r1, r2, r3;
                    ldsm4(r0, r1, r2, r3, bbase + ks * 32);
                    uint32_t bb0[2] = {r0, r1};
                    mma16816(S[2 * j2], qf[ks], bb0);
                    uint32_t bb1[2] = {r2, r3};
                    mma16816(S[2 * j2 + 1], qf[ks], bb1);
                }
            }
        }

        // ---- scale + causal mask ----
        int kv0 = kt * 64;
        bool msk = (kt >= nkt - 2);
#pragma unroll
        for (int j = 0; j < 8; j++) {
            S[j][0] *= sm_scale; S[j][1] *= sm_scale;
            S[j][2] *= sm_scale; S[j][3] *= sm_scale;
            if (msk) {
                int c0 = kv0 + j * 8 + 2 * (lane & 3);
                if (c0 > r0g)     S[j][0] = -1e9f;
                if (c0 + 1 > r0g) S[j][1] = -1e9f;
                if (c0 > r0g + 8)     S[j][2] = -1e9f;
                if (c0 + 1 > r0g + 8) S[j][3] = -1e9f;
            }
        }

        // ---- online softmax ----
        float mx0 = -1e30f, mx1 = -1e30f;
#pragma unroll
        for (int j = 0; j < 8; j++) {
            mx0 = fmaxf(mx0, fmaxf(S[j][0], S[j][1]));
            mx1 = fmaxf(mx1, fmaxf(S[j][2], S[j][3]));
        }
        mx0 = fmaxf(mx0, __shfl_xor_sync(0xffffffffu, mx0, 1));
        mx0 = fmaxf(mx0, __shfl_xor_sync(0xffffffffu, mx0, 2));
        mx1 = fmaxf(mx1, __shfl_xor_sync(0xffffffffu, mx1, 1));
        mx1 = fmaxf(mx1, __shfl_xor_sync(0xffffffffu, mx1, 2));
        float m0n = fmaxf(m0, mx0), m1n = fmaxf(m1, mx1);
        float c0f = __expf(m0 - m0n), c1f = __expf(m1 - m1n);
        float s0 = 0.f, s1 = 0.f;
#pragma unroll
        for (int j = 0; j < 8; j++) {
            S[j][0] = __expf(S[j][0] - m0n);
            S[j][1] = __expf(S[j][1] - m0n);
            S[j][2] = __expf(S[j][2] - m1n);
            S[j][3] = __expf(S[j][3] - m1n);
            s0 += S[j][0] + S[j][1];
            s1 += S[j][2] + S[j][3];
        }
        s0 += __shfl_xor_sync(0xffffffffu, s0, 1);
        s0 += __shfl_xor_sync(0xffffffffu, s0, 2);
        s1 += __shfl_xor_sync(0xffffffffu, s1, 1);
        s1 += __shfl_xor_sync(0xffffffffu, s1, 2);
        l0 = l0 * c0f + s0;
        l1 = l1 * c1f + s1;
        m0 = m0n; m1 = m1n;
#pragma unroll
        for (int j = 0; j < 16; j++) {
            O[j][0] *= c0f; O[j][1] *= c0f;
            O[j][2] *= c1f; O[j][3] *= c1f;
        }

        // ---- O += P V ----
        {
            uint32_t vbase = cur + KSTG;
            uint32_t bvo = (uint32_t)((lane & 7) + ((lane >> 4) << 3)) * VRB
                         + (((lane >> 3) & 1) << 4);
#pragma unroll
            for (int kk = 0; kk < 4; kk++) {
                uint32_t pf[4];
                pf[0] = h2_as_u32(__floats2half2_rn(S[2 * kk][0], S[2 * kk][1]));
                pf[1] = h2_as_u32(__floats2half2_rn(S[2 * kk][2], S[2 * kk][3]));
                pf[2] = h2_as_u32(__floats2half2_rn(S[2 * kk + 1][0], S[2 * kk + 1][1]));
                pf[3] = h2_as_u32(__floats2half2_rn(S[2 * kk + 1][2], S[2 * kk + 1][3]));
#pragma unroll
                for (int j2 = 0; j2 < 8; j2++) {
                    uint32_t r0, r1, r2, r3;
                    ldsm4(r0, r1, r2, r3, vbase + bvo + j2 * 16 * VRB + kk * 32);
                    uint32_t bb0[2] = {r0, r1};
                    mma16816(O[2 * j2], pf, bb0);
                    uint32_t bb1[2] = {r2, r3};
                    mma16816(O[2 * j2 + 1], pf, bb1);
                }
            }
        }
        __syncthreads();
    }

    // ---- epilogue ----
    float i0 = 1.f / l0, i1 = 1.f / l1;
    int row0 = q0 + w * 16 + (lane >> 2);
#pragma unroll
    for (int j = 0; j < 16; j++) {
        int col = hbase + j * 8 + 2 * (lane & 3);
        *(__half2*)(ctx + (size_t)row0 * DD + col) =
            __floats2half2_rn(O[j][0] * i0, O[j][1] * i0);
        *(__half2*)(ctx + (size_t)(row0 + 8) * DD + col) =
            __floats2half2_rn(O[j][2] * i1, O[j][3] * i1);
    }
}

// ---------------- launch ----------------------------------------------------
extern "C" void kernel_launch(void* const* d_in, const int* in_sizes, int n_in,
                              void* d_out, int out_size) {
    const float* x      = (const float*)d_in[0];
    const float* scale  = (const float*)d_in[2];
    const float* offset = (const float*)d_in[3];
    const float* wq     = (const float*)d_in[4];
    const float* wk     = (const float*)d_in[5];
    const float* wv     = (const float*)d_in[6];
    const float* wo     = (const float*)d_in[7];
    const float* w1     = (const float*)d_in[8];
    const float* b1     = (const float*)d_in[9];
    const float* w2     = (const float*)d_in[10];
    const float* b2     = (const float*)d_in[11];
    float* out = (float*)d_out;

    __half *xn, *ctx, *ffh, *wqt, *wkt, *wvt, *wot, *w1t, *w2t, *qh, *kh, *vt;
    float *q, *k, *v;
    cudaGetSymbolAddress((void**)&xn, g_xn);
    cudaGetSymbolAddress((void**)&q, g_q);
    cudaGetSymbolAddress((void**)&k, g_k);
    cudaGetSymbolAddress((void**)&v, g_v);
    cudaGetSymbolAddress((void**)&qh, g_qh);
    cudaGetSymbolAddress((void**)&kh, g_kh);
    cudaGetSymbolAddress((void**)&vt, g_vt);
    cudaGetSymbolAddress((void**)&ctx, g_ctx);
    cudaGetSymbolAddress((void**)&ffh, g_ffh);
    cudaGetSymbolAddress((void**)&wqt, g_wqt);
    cudaGetSymbolAddress((void**)&wkt, g_wkt);
    cudaGetSymbolAddress((void**)&wvt, g_wvt);
    cudaGetSymbolAddress((void**)&wot, g_wot);
    cudaGetSymbolAddress((void**)&w1t, g_w1t);
    cudaGetSymbolAddress((void**)&w2t, g_w2t);

    cudaFuncSetAttribute(attn_mma,
                         cudaFuncAttributeMaxDynamicSharedMemorySize, ASMEM);

    dim3 tb(32, 8);
    transpose_half<<<dim3(DD / 32, DD / 32), tb>>>(wq, wqt, DD, DD);
    transpose_half<<<dim3(DD / 32, DD / 32), tb>>>(wk, wkt, DD, DD);
    transpose_half<<<dim3(DD / 32, DD / 32), tb>>>(wv, wvt, DD, DD);
    transpose_half<<<dim3(DD / 32, DD / 32), tb>>>(wo, wot, DD, DD);
    transpose_half<<<dim3(FFD / 32, DD / 32), tb>>>(w1, w1t, DD, FFD);
    transpose_half<<<dim3(DD / 32, FFD / 32), tb>>>(w2, w2t, FFD, DD);

    layernorm_kernel<<<TT, 256>>>(x, scale, offset, xn);

    dim3 gD(DD / 128, TT / 128);
    gemm_hmma<<<gD, 256, GSMEM>>>(xn, wqt, TT, DD, DD, q, nullptr, nullptr, nullptr, 0);
    gemm_hmma<<<gD, 256, GSMEM>>>(xn, wkt, TT, DD, DD, k, nullptr, nullptr, nullptr, 0);
    gemm_hmma<<<gD, 256, GSMEM>>>(xn, wvt, TT, DD, DD, v, nullptr, nullptr, nullptr, 0);

    rope_half<<<(TT * HH * 64) / 256, 256>>>(q, k, qh, kh);
    transpose_vt<<<dim3(DD / 32, TT / 32), tb>>>(v, vt);

    attn_mma<<<dim3(TT / 128, HH), 256, ASMEM>>>(qh, kh, vt, ctx);

    // out = ctx @ wo + x
    gemm_hmma<<<gD, 256, GSMEM>>>(ctx, wot, TT, DD, DD, out, nullptr, nullptr, x, 2);
    // ffh = fp16(gelu(xn @ w1 + b1))
    gemm_hmma<<<dim3(FFD / 128, TT / 128), 256, GSMEM>>>(xn, w1t, TT, FFD, DD,
                                                         nullptr, ffh, b1, nullptr, 1);
    // out += ffh @ w2 + b2
    gemm_hmma<<<gD, 256, GSMEM>>>(ffh, w2t, TT, DD, FFD, out, nullptr, b2, nullptr, 3);
}